// round 9
// baseline (speedup 1.0000x reference)
#include <cuda_runtime.h>
#include <cuda_bf16.h>
#include <math.h>
#include <stdint.h>

// ---------------------------------------------------------------------------
// VectorQuantizerEMA (N=32768, K=8192, D=512)
// Single bf16 GEMM (exact -|e|^2/2 in acc init) + global top-4 exact refine.
// R9: BM=256 x BN=128 tiles, 64x64 warp tiles, occ-1 persistent, 5-stage ring.
// ---------------------------------------------------------------------------
#define NTOK 32768
#define KCODE 8192
#define DDIM 512

#define DECAY 0.99f
#define ONE_MINUS_DECAY 0.01f
#define EPS 1e-5f
#define COMMIT 0.25f

#define OQ  ((size_t)0)
#define OL  ((size_t)(NTOK) * DDIM)
#define OP  (OL + 1)
#define OE  (OP + 1)
#define OC  (OE + (size_t)KCODE * DDIM)
#define OW  (OC + KCODE)

// ------------------------- device scratch (no alloc) -----------------------
__device__ float          g_halfE2[KCODE];
__device__ int            g_idx[NTOK];
__device__ float          g_cs[KCODE];
__device__ float          g_newcs[KCODE];
__device__ float          g_dw[(size_t)KCODE * DDIM];
__device__ double         g_loss;
__device__ __nv_bfloat16  g_xb[(size_t)NTOK * DDIM];
__device__ __nv_bfloat16  g_eb[(size_t)KCODE * DDIM];
__device__ float4         g_cand[(size_t)NTOK * 64];   // [token][ct] {v1,v2,i1,i2}

// ------------------------- helpers -----------------------------------------
__device__ __forceinline__ uint32_t smem_u32(const void* p) {
    uint32_t a;
    asm("{ .reg .u64 t; cvta.to.shared.u64 t, %1; cvt.u32.u64 %0, t; }" : "=r"(a) : "l"(p));
    return a;
}
__device__ __forceinline__ void cp16(uint32_t dst, const void* src) {
    asm volatile("cp.async.cg.shared.global [%0], [%1], 16;" :: "r"(dst), "l"(src));
}
#define CP_COMMIT() asm volatile("cp.async.commit_group;" ::: "memory")

__device__ __forceinline__ void ldm_x4(uint32_t addr, uint32_t& r0, uint32_t& r1,
                                       uint32_t& r2, uint32_t& r3) {
    asm volatile("ldmatrix.sync.aligned.m8n8.x4.shared.b16 {%0,%1,%2,%3}, [%4];"
                 : "=r"(r0), "=r"(r1), "=r"(r2), "=r"(r3) : "r"(addr));
}
__device__ __forceinline__ void mma16816(float* d, const uint32_t* a, const uint32_t* b) {
    asm volatile("mma.sync.aligned.m16n8k16.row.col.f32.bf16.bf16.f32 "
                 "{%0,%1,%2,%3}, {%4,%5,%6,%7}, {%8,%9}, {%0,%1,%2,%3};"
                 : "+f"(d[0]), "+f"(d[1]), "+f"(d[2]), "+f"(d[3])
                 : "r"(a[0]), "r"(a[1]), "r"(a[2]), "r"(a[3]), "r"(b[0]), "r"(b[1]));
}
__device__ __forceinline__ void merge2(float& t1v, int& t1i, float& t2v, int& t2i,
                                       float o1v, int o1i, float o2v, int o2i) {
    if (o1v > t1v) {
        float n2v = t1v; int n2i = t1i;
        if (o2v > n2v) { n2v = o2v; n2i = o2i; }
        t1v = o1v; t1i = o1i; t2v = n2v; t2i = n2i;
    } else if (o1v > t2v) {
        t2v = o1v; t2i = o1i;
    }
}
__device__ __forceinline__ void ins4(float* v, int* ix, float ov, int oi) {
    if (ov > v[3]) {
        if (ov > v[2]) {
            v[3] = v[2]; ix[3] = ix[2];
            if (ov > v[1]) {
                v[2] = v[1]; ix[2] = ix[1];
                if (ov > v[0]) { v[1] = v[0]; ix[1] = ix[0]; v[0] = ov; ix[0] = oi; }
                else { v[1] = ov; ix[1] = oi; }
            } else { v[2] = ov; ix[2] = oi; }
        } else { v[3] = ov; ix[3] = oi; }
    }
}

// ---------------------------------------------------------------------------
// K0a: E -> bf16, half-norms, zero scratch
// ---------------------------------------------------------------------------
__global__ void k_prep(const float* __restrict__ E) {
    int k = blockIdx.x;
    int t = threadIdx.x;
    const float* row = E + (size_t)k * DDIM;
    float e0 = row[t], e1 = row[t + 256];

    g_eb[(size_t)k * DDIM + t]       = __float2bfloat16_rn(e0);
    g_eb[(size_t)k * DDIM + t + 256] = __float2bfloat16_rn(e1);

    float s = e0 * e0 + e1 * e1;
    __shared__ float sh[8];
    int lane = t & 31, w = t >> 5;
    #pragma unroll
    for (int o = 16; o; o >>= 1) s += __shfl_down_sync(0xffffffffu, s, o);
    if (lane == 0) sh[w] = s;
    __syncthreads();
    if (w == 0) {
        float v = (lane < 8) ? sh[lane] : 0.f;
        #pragma unroll
        for (int o = 4; o; o >>= 1) v += __shfl_down_sync(0xffffffffu, v, o);
        if (lane == 0) g_halfE2[k] = 0.5f * v;
    }
    float* dwr = g_dw + (size_t)k * DDIM;
    dwr[t] = 0.f;
    dwr[t + 256] = 0.f;
    if (t == 0) g_cs[k] = 0.f;
    if (k == 0 && t == 0) g_loss = 0.0;
}

// K0b: X -> bf16
__global__ void k_cvtx(const float* __restrict__ X) {
    size_t i = (size_t)blockIdx.x * 256 + threadIdx.x;
    g_xb[i] = __float2bfloat16_rn(X[i]);
}

// ---------------------------------------------------------------------------
// K1: persistent bf16 GEMM + per-tile top-2.
// Item = (m-tile 0..127, ct 0..63): 256x128 tile, 16 BK=32 chunks.
// 148 CTAs (occ 1), 8 warps as 4x2 of 64x64, flat chunk stream, 5-stage ring.
// ---------------------------------------------------------------------------
#define BM 256
#define BN 128
#define BK 32
#define KCH 16
#define NITEMS (128 * 64)            // 8192
#define NCTA 148
#define SROW 40                      // bf16 stride (32 + 8 pad) = 80 B
#define SROWB (SROW * 2)
#define STAGE_A (BM * SROWB)         // 20480 B
#define STAGE_B (BN * SROWB)         // 10240 B
#define STAGE_SZ (STAGE_A + STAGE_B) // 30720 B
#define NSTAGE 5
#define RED_OFF (NSTAGE * STAGE_SZ)  // 153600
#define GEMM_SMEM (RED_OFF + 8192)   // 161792 B

__device__ __forceinline__ void load_flat(int gflat, int slot, int i0,
                                          uint32_t sb, int tid) {
    const int item = i0 + (gflat >> 4);
    const int kc = gflat & 15;
    const int m0 = (item >> 6) * BM;
    const int n0 = (item & 63) * BN;
    const int koff = kc * BK;
    const uint32_t stA = sb + slot * STAGE_SZ;
    const uint32_t stB = stA + STAGE_A;
    #pragma unroll
    for (int i = 0; i < 4; i++) {                 // A: 1024 cp16
        int idx = tid + i * 256;
        int row = idx >> 2, c = idx & 3;
        cp16(stA + row * SROWB + c * 16,
             g_xb + (size_t)(m0 + row) * DDIM + koff + c * 8);
    }
    #pragma unroll
    for (int i = 0; i < 2; i++) {                 // B: 512 cp16
        int idx = tid + i * 256;
        int row = idx >> 2, c = idx & 3;
        cp16(stB + row * SROWB + c * 16,
             g_eb + (size_t)(n0 + row) * DDIM + koff + c * 8);
    }
    CP_COMMIT();
}

__global__ __launch_bounds__(256, 1)
void k_gemm() {
    extern __shared__ char smem[];
    const uint32_t sb = smem_u32(smem);
    const int tid = threadIdx.x;
    const int wid = tid >> 5;
    const int lane = tid & 31;
    const int wm = wid >> 1;          // 0..3 : rows wm*64
    const int wn = wid & 1;           // 0..1 : cols wn*64
    const int bid = blockIdx.x;

    // static contiguous item ranges: 8192 = 148*55 + 52
    const int base = NITEMS / NCTA;              // 55
    const int rem  = NITEMS - base * NCTA;       // 52
    const int i0   = bid * base + (bid < rem ? bid : rem);
    const int cnt  = base + (bid < rem ? 1 : 0);
    const int T    = cnt * KCH;

    // ldsm lane addressing
    const uint32_t a_off = (uint32_t)(wm * 64 + (lane & 15)) * SROWB + (lane >> 4) * 16;
    const uint32_t b_row = (uint32_t)(wn * 64 + (lane & 7) + ((lane >> 4) << 3));
    const uint32_t b_off = b_row * SROWB + ((lane >> 3) & 1) * 16;

    load_flat(0, 0, i0, sb, tid);
    load_flat(1, 1, i0, sb, tid);
    load_flat(2, 2, i0, sb, tid);
    load_flat(3, 3, i0, sb, tid);

    float acc[4][8][4];
    int slot = 0;        // compute slot for chunk g
    int pslot = 4;       // prefetch slot for chunk g+4

    for (int g = 0; g < T; ++g) {
        const int kc = g & 15;
        const int item = i0 + (g >> 4);
        const int n0 = (item & 63) * BN;

        if (kc == 0) {
            #pragma unroll
            for (int nf = 0; nf < 8; nf++) {
                int col = n0 + wn * 64 + nf * 8 + (lane & 3) * 2;
                float2 h = *(const float2*)(&g_halfE2[col]);
                #pragma unroll
                for (int mf = 0; mf < 4; mf++) {
                    acc[mf][nf][0] = -h.x; acc[mf][nf][1] = -h.y;
                    acc[mf][nf][2] = -h.x; acc[mf][nf][3] = -h.y;
                }
            }
        }

        const int pa = T - 1 - g;
        if (pa >= 3)      asm volatile("cp.async.wait_group 3;" ::: "memory");
        else if (pa == 2) asm volatile("cp.async.wait_group 2;" ::: "memory");
        else if (pa == 1) asm volatile("cp.async.wait_group 1;" ::: "memory");
        else              asm volatile("cp.async.wait_group 0;" ::: "memory");
        __syncthreads();

        const uint32_t stA = sb + slot * STAGE_SZ;
        const uint32_t stB = stA + STAGE_A;
        #pragma unroll
        for (int ks = 0; ks < 2; ks++) {
            uint32_t a[4][4];
            #pragma unroll
            for (int mf = 0; mf < 4; mf++)
                ldm_x4(stA + a_off + ks * 32 + mf * (16 * SROWB),
                       a[mf][0], a[mf][1], a[mf][2], a[mf][3]);
            uint32_t b[8][2];
            #pragma unroll
            for (int np = 0; np < 4; np++) {
                uint32_t r0, r1, r2, r3;
                ldm_x4(stB + b_off + ks * 32 + np * (16 * SROWB), r0, r1, r2, r3);
                b[np * 2][0] = r0; b[np * 2][1] = r1;
                b[np * 2 + 1][0] = r2; b[np * 2 + 1][1] = r3;
            }
            #pragma unroll
            for (int mf = 0; mf < 4; mf++)
                #pragma unroll
                for (int nf = 0; nf < 8; nf++)
                    mma16816(acc[mf][nf], a[mf], b[nf]);
        }
        if (g + 4 < T) load_flat(g + 4, pslot, i0, sb, tid);
        if (++slot == NSTAGE) slot = 0;
        if (++pslot == NSTAGE) pslot = 0;

        if (kc == KCH - 1) {
            // ---- per-item top-2 epilogue ----
            const int m0 = (item >> 6) * BM;
            const int ct = item & 63;
            float t1v[8], t2v[8];
            int   t1i[8], t2i[8];
            #pragma unroll
            for (int s = 0; s < 8; s++) { t1v[s] = -3.0e38f; t2v[s] = -3.0e38f; t1i[s] = 0; t2i[s] = 0; }
            #pragma unroll
            for (int mf = 0; mf < 4; mf++)
                #pragma unroll
                for (int h = 0; h < 2; h++) {
                    int s = mf * 2 + h;
                    #pragma unroll
                    for (int nf = 0; nf < 8; nf++) {
                        int colb = n0 + wn * 64 + nf * 8 + (lane & 3) * 2;
                        float v0 = acc[mf][nf][h * 2 + 0];
                        float v1 = acc[mf][nf][h * 2 + 1];
                        if (v0 > t1v[s]) { t2v[s] = t1v[s]; t2i[s] = t1i[s]; t1v[s] = v0; t1i[s] = colb; }
                        else if (v0 > t2v[s]) { t2v[s] = v0; t2i[s] = colb; }
                        if (v1 > t1v[s]) { t2v[s] = t1v[s]; t2i[s] = t1i[s]; t1v[s] = v1; t1i[s] = colb + 1; }
                        else if (v1 > t2v[s]) { t2v[s] = v1; t2i[s] = colb + 1; }
                    }
                }
            #pragma unroll
            for (int s = 0; s < 8; s++) {
                #pragma unroll
                for (int d = 1; d <= 2; d <<= 1) {
                    float o1v = __shfl_xor_sync(0xffffffffu, t1v[s], d);
                    int   o1i = __shfl_xor_sync(0xffffffffu, t1i[s], d);
                    float o2v = __shfl_xor_sync(0xffffffffu, t2v[s], d);
                    int   o2i = __shfl_xor_sync(0xffffffffu, t2i[s], d);
                    merge2(t1v[s], t1i[s], t2v[s], t2i[s], o1v, o1i, o2v, o2i);
                }
            }
            __syncthreads();
            float* c_v = (float*)(smem + RED_OFF);            // [256][2][2]
            int*   c_i = (int*)(smem + RED_OFF + 4096);       // [256][2][2]
            if ((lane & 3) == 0) {
                #pragma unroll
                for (int s = 0; s < 8; s++) {
                    int mf = s >> 1, h = s & 1;
                    int row = wm * 64 + mf * 16 + h * 8 + (lane >> 2);
                    c_v[(row * 2 + wn) * 2 + 0] = t1v[s];
                    c_v[(row * 2 + wn) * 2 + 1] = t2v[s];
                    c_i[(row * 2 + wn) * 2 + 0] = t1i[s];
                    c_i[(row * 2 + wn) * 2 + 1] = t2i[s];
                }
            }
            __syncthreads();
            {
                float v1 = c_v[(tid * 2) * 2 + 0], v2 = c_v[(tid * 2) * 2 + 1];
                int   i1 = c_i[(tid * 2) * 2 + 0], i2 = c_i[(tid * 2) * 2 + 1];
                merge2(v1, i1, v2, i2,
                       c_v[(tid * 2 + 1) * 2 + 0], c_i[(tid * 2 + 1) * 2 + 0],
                       c_v[(tid * 2 + 1) * 2 + 1], c_i[(tid * 2 + 1) * 2 + 1]);
                g_cand[(size_t)(m0 + tid) * 64 + ct] =
                    make_float4(v1, v2, __int_as_float(i1), __int_as_float(i2));
            }
        }
    }
}

// ---------------------------------------------------------------------------
// K1b: merge 64 tile-candidates -> global top-4, exact fp32 rescore.
// One warp per token.
// ---------------------------------------------------------------------------
__global__ void k_refine(const float* __restrict__ X, const float* __restrict__ E) {
    const int n = blockIdx.x * 8 + (threadIdx.x >> 5);
    const int lane = threadIdx.x & 31;

    float4 cA = g_cand[(size_t)n * 64 + lane];
    float4 cB = g_cand[(size_t)n * 64 + lane + 32];

    float v[4]; int ix[4];
    v[0] = -3.0e38f; v[1] = -3.0e38f; v[2] = -3.0e38f; v[3] = -3.0e38f;
    ix[0] = ix[1] = ix[2] = ix[3] = 0;
    ins4(v, ix, cA.x, __float_as_int(cA.z));
    ins4(v, ix, cA.y, __float_as_int(cA.w));
    ins4(v, ix, cB.x, __float_as_int(cB.z));
    ins4(v, ix, cB.y, __float_as_int(cB.w));

    #pragma unroll
    for (int d = 16; d; d >>= 1) {
        float ov[4]; int oi[4];
        #pragma unroll
        for (int s = 0; s < 4; s++) {
            ov[s] = __shfl_xor_sync(0xffffffffu, v[s], d);
            oi[s] = __shfl_xor_sync(0xffffffffu, ix[s], d);
        }
        #pragma unroll
        for (int s = 0; s < 4; s++) ins4(v, ix, ov[s], oi[s]);
    }

    float xr[16];
    const float* x = X + (size_t)n * DDIM;
    #pragma unroll
    for (int i = 0; i < 16; i++) xr[i] = x[lane + i * 32];

    float sc[4];
    #pragma unroll
    for (int c = 0; c < 4; c++) {
        const float* e = E + (size_t)ix[c] * DDIM;
        float s = 0.f;
        #pragma unroll
        for (int i = 0; i < 16; i++) s = fmaf(xr[i], e[lane + i * 32], s);
        #pragma unroll
        for (int o = 16; o; o >>= 1) s += __shfl_xor_sync(0xffffffffu, s, o);
        sc[c] = s - g_halfE2[ix[c]];
    }
    if (lane == 0) {
        float bv = sc[0]; int bi = ix[0];
        #pragma unroll
        for (int c = 1; c < 4; c++) {
            if (sc[c] > bv || (sc[c] == bv && ix[c] < bi)) { bv = sc[c]; bi = ix[c]; }
        }
        g_idx[n] = bi;
    }
}

// ---------------------------------------------------------------------------
// K2: gather + straight-through output, loss, scatter cs/dw
// ---------------------------------------------------------------------------
__global__ void k_scatter(const float* __restrict__ X, const float* __restrict__ E,
                          float* __restrict__ out) {
    int n = blockIdx.x;
    int k = g_idx[n];
    int t = threadIdx.x;

    float4 x = *(const float4*)(X + (size_t)n * DDIM + t * 4);
    float4 q = *(const float4*)(E + (size_t)k * DDIM + t * 4);
    float dx = q.x - x.x, dy = q.y - x.y, dz = q.z - x.z, dw = q.w - x.w;
    float4 o;
    o.x = x.x + dx; o.y = x.y + dy; o.z = x.z + dz; o.w = x.w + dw;
    *(float4*)(out + OQ + (size_t)n * DDIM + t * 4) = o;

    float ls = dx * dx + dy * dy + dz * dz + dw * dw;
    __shared__ float sh[4];
    int lane = t & 31, w = t >> 5;
    #pragma unroll
    for (int oo = 16; oo; oo >>= 1) ls += __shfl_down_sync(0xffffffffu, ls, oo);
    if (lane == 0) sh[w] = ls;
    __syncthreads();
    if (t == 0) {
        float s = sh[0] + sh[1] + sh[2] + sh[3];
        atomicAdd(&g_loss, (double)s);
        atomicAdd(&g_cs[k], 1.0f);
    }

    float* dwr = g_dw + (size_t)k * DDIM + t * 4;
    atomicAdd(dwr + 0, x.x);
    atomicAdd(dwr + 1, x.y);
    atomicAdd(dwr + 2, x.z);
    atomicAdd(dwr + 3, x.w);
}

// K3: stats
__global__ __launch_bounds__(1024, 1)
void k_stats(const float* __restrict__ ema_cs, float* __restrict__ out) {
    int t = threadIdx.x;
    float pre[8];
    double s_pre = 0.0, s_ent = 0.0;
    #pragma unroll
    for (int i = 0; i < 8; i++) {
        int k = t + i * 1024;
        float cs = g_cs[k];
        pre[i] = ema_cs[k] * DECAY + ONE_MINUS_DECAY * cs;
        s_pre += (double)pre[i];
        float p = cs * (1.0f / (float)NTOK);
        s_ent += (double)(p * logf(p + 1e-10f));
    }
    __shared__ double shp[32], she[32];
    int lane = t & 31, w = t >> 5;
    #pragma unroll
    for (int o = 16; o; o >>= 1) {
        s_pre += __shfl_down_sync(0xffffffffu, s_pre, o);
        s_ent += __shfl_down_sync(0xffffffffu, s_ent, o);
    }
    if (lane == 0) { shp[w] = s_pre; she[w] = s_ent; }
    __syncthreads();
    __shared__ double tot_pre_s, tot_ent_s;
    if (w == 0) {
        double vp = shp[lane], ve = she[lane];
        #pragma unroll
        for (int o = 16; o; o >>= 1) {
            vp += __shfl_down_sync(0xffffffffu, vp, o);
            ve += __shfl_down_sync(0xffffffffu, ve, o);
        }
        if (lane == 0) { tot_pre_s = vp; tot_ent_s = ve; }
    }
    __syncthreads();
    float ntot = (float)tot_pre_s;
    float denom = ntot + (float)KCODE * EPS;
    #pragma unroll
    for (int i = 0; i < 8; i++) {
        int k = t + i * 1024;
        float ncs = (pre[i] + EPS) / denom * ntot;
        g_newcs[k] = ncs;
        out[OC + k] = ncs;
    }
    if (t == 0) {
        out[OL] = (float)(COMMIT * g_loss / ((double)NTOK * (double)DDIM));
        out[OP] = (float)exp(-tot_ent_s);
    }
}

// K4: EMA updates (float2: OE/OW only 8B aligned)
__global__ void k_ema(const float* __restrict__ ema_w, float* __restrict__ out) {
    size_t gi = (size_t)blockIdx.x * blockDim.x + threadIdx.x;
    int k = (int)(gi >> 8);
    float ncs = g_newcs[k];
    float2 w = *(const float2*)(ema_w + gi * 2);
    float2 d = *(const float2*)(g_dw + gi * 2);
    float2 ew;
    ew.x = w.x * DECAY + ONE_MINUS_DECAY * d.x;
    ew.y = w.y * DECAY + ONE_MINUS_DECAY * d.y;
    *(float2*)(out + OW + gi * 2) = ew;
    float2 eb;
    eb.x = ew.x / ncs; eb.y = ew.y / ncs;
    *(float2*)(out + OE + gi * 2) = eb;
}

// ---------------------------------------------------------------------------
extern "C" void kernel_launch(void* const* d_in, const int* in_sizes, int n_in,
                              void* d_out, int out_size) {
    const float* X   = (const float*)d_in[0];
    const float* E   = (const float*)d_in[1];
    const float* ECS = (const float*)d_in[2];
    const float* EW  = (const float*)d_in[3];
    float* out = (float*)d_out;

    cudaFuncSetAttribute(k_gemm, cudaFuncAttributeMaxDynamicSharedMemorySize, GEMM_SMEM);

    k_prep<<<KCODE, 256>>>(E);
    k_cvtx<<<(NTOK * DDIM) / 256, 256>>>(X);
    k_gemm<<<NCTA, 256, GEMM_SMEM>>>();
    k_refine<<<NTOK / 8, 256>>>(X, E);
    k_scatter<<<NTOK, 128>>>(X, E, out);
    k_stats<<<1, 1024>>>(ECS, out);
    k_ema<<<(KCODE * DDIM / 2) / 256, 256>>>(EW, out);
}